// round 4
// baseline (speedup 1.0000x reference)
#include <cuda_runtime.h>

// Problem constants (fixed by setup_inputs)
#define BB   2
#define NN   16384
#define CC   64
#define SS   4096
#define KK   32
#define R2   0.16f
#define CIN  67
#define H3   128

#define OUT_F (BB*SS*3)              /* 24576  : new_xyz region     */
#define OUT_I (OUT_F + BB*H3*SS)     /* 1073152: samp_idx region    */

#define SU   69   /* dup-activation buffer k-stride, in ull units (odd -> conflict-free) */

// Scratch (device globals — no allocation allowed)
__device__ float4 g_pts[BB*NN];          // x,y,z,|p|^2
__device__ float  g_featT[BB*NN*CC];     // [B][N][C]
__device__ int    g_idx[BB*SS*KK];       // ball query result
__device__ int    g_tick;                // work-stealing ticket for k_ball

// ---- packed f32x2 helpers (FFMA2: 2x fp32 FMA rate, PTX-only) -------------
typedef unsigned long long ull;
__device__ __forceinline__ ull pk2(float lo, float hi) {
    ull r; asm("mov.b64 %0,{%1,%2};" : "=l"(r) : "f"(lo), "f"(hi)); return r;
}
__device__ __forceinline__ void upk2(ull v, float& lo, float& hi) {
    asm("mov.b64 {%0,%1},%2;" : "=f"(lo), "=f"(hi) : "l"(v));
}
__device__ __forceinline__ ull ffma2(ull a, ull b, ull c) {
    ull d; asm("fma.rn.f32x2 %0,%1,%2,%3;" : "=l"(d) : "l"(a), "l"(b), "l"(c));
    return d;
}
__device__ __forceinline__ ull ldp(const float* p) {   // aligned smem pair
    return *reinterpret_cast<const ull*>(p);
}

// ---------------------------------------------------------------------------
__global__ void k_prep(const float* __restrict__ xyz) {
    int i = blockIdx.x * blockDim.x + threadIdx.x;
    if (i == 0) g_tick = 0;                    // reset stealing ticket every launch
    if (i < BB*NN) {
        float x = xyz[3*i+0], y = xyz[3*i+1], z = xyz[3*i+2];
        g_pts[i] = make_float4(x, y, z, fmaf(z, z, fmaf(y, y, x*x)));
    }
}

// Transpose features [B,C,N] -> [B,N,C]
__global__ void k_trans(const float* __restrict__ feat) {
    __shared__ float tile[32][33];
    int b  = blockIdx.z;
    int n0 = blockIdx.x * 32, c0 = blockIdx.y * 32;
    int tx = threadIdx.x, ty = threadIdx.y;
    #pragma unroll
    for (int i = ty; i < 32; i += 8)
        tile[i][tx] = feat[(size_t)b*CC*NN + (size_t)(c0+i)*NN + (n0+tx)];
    __syncthreads();
    #pragma unroll
    for (int i = ty; i < 32; i += 8)
        g_featT[(size_t)b*NN*CC + (size_t)(n0+i)*CC + (c0+tx)] = tile[tx][i];
}

// new_xyz copy + samp_idx
__global__ void k_outs(const float* __restrict__ xyz, float* __restrict__ out) {
    int i = blockIdx.x * blockDim.x + threadIdx.x;
    if (i < BB*SS) {
        int b = i / SS, s = i % SS;
        out[3*i+0] = xyz[(size_t)(b*NN+s)*3 + 0];
        out[3*i+1] = xyz[(size_t)(b*NN+s)*3 + 1];
        out[3*i+2] = xyz[(size_t)(b*NN+s)*3 + 2];
        out[OUT_I + i] = (float)s;
    }
}

// ---------------------------------------------------------------------------
// Ball query with warp-level work stealing (heavy centroids scan all N; ticket
// balancing removes the block-tail). x4 unroll for MLP=4. Ordered scan with
// ballot+popc; matches reference semantics exactly.
__global__ void k_ball() {
    __shared__ int sbuf[8][KK];
    int w    = threadIdx.x >> 5;
    int lane = threadIdx.x & 31;
    unsigned lmask = (1u << lane) - 1u;
    unsigned lbit  = 1u << lane;

    for (;;) {
        int gw;
        if (lane == 0) gw = atomicAdd(&g_tick, 1);
        gw = __shfl_sync(0xffffffffu, gw, 0);
        if (gw >= BB*SS) break;

        int b = gw / SS, s = gw % SS;
        int base0 = b * NN;
        float4 c4 = g_pts[base0 + s];
        int cnt = 0;
        for (int base = 0; base < NN; base += 128) {
            float4 p0 = g_pts[base0 + base + lane];
            float4 p1 = g_pts[base0 + base + 32  + lane];
            float4 p2 = g_pts[base0 + base + 64  + lane];
            float4 p3 = g_pts[base0 + base + 96  + lane];
            float d0 = c4.w + p0.w - 2.0f*(c4.x*p0.x + c4.y*p0.y + c4.z*p0.z);
            float d1 = c4.w + p1.w - 2.0f*(c4.x*p1.x + c4.y*p1.y + c4.z*p1.z);
            float d2 = c4.w + p2.w - 2.0f*(c4.x*p2.x + c4.y*p2.y + c4.z*p2.z);
            float d3 = c4.w + p3.w - 2.0f*(c4.x*p3.x + c4.y*p3.y + c4.z*p3.z);
            unsigned m0 = __ballot_sync(0xffffffffu, d0 < R2);
            unsigned m1 = __ballot_sync(0xffffffffu, d1 < R2);
            unsigned m2 = __ballot_sync(0xffffffffu, d2 < R2);
            unsigned m3 = __ballot_sync(0xffffffffu, d3 < R2);
            if (m0 & lbit) {
                int pos = cnt + __popc(m0 & lmask);
                if (pos < KK) sbuf[w][pos] = base + lane;
            }
            cnt += __popc(m0);
            if (m1 & lbit) {
                int pos = cnt + __popc(m1 & lmask);
                if (pos < KK) sbuf[w][pos] = base + 32 + lane;
            }
            cnt += __popc(m1);
            if (m2 & lbit) {
                int pos = cnt + __popc(m2 & lmask);
                if (pos < KK) sbuf[w][pos] = base + 64 + lane;
            }
            cnt += __popc(m2);
            if (m3 & lbit) {
                int pos = cnt + __popc(m3 & lmask);
                if (pos < KK) sbuf[w][pos] = base + 96 + lane;
            }
            cnt += __popc(m3);
            if (cnt >= KK) break;
        }
        __syncwarp();
        int v = 0;
        if (cnt > 0) {
            int first = sbuf[w][0];
            v = (lane < cnt) ? sbuf[w][lane] : first;
        }
        g_idx[gw*KK + lane] = v;
        // __shfl_sync at loop top re-converges before sbuf is overwritten
    }
}

// ---------------------------------------------------------------------------
// Fused gather + 3-layer MLP + max-pool, FFMA2 with DUPLICATED activations:
// activations live in smem as (v,v) 8-byte pairs, so the hot loop is pure
// LDS.64 + FFMA2 (no register packs -> alu pipe idle, fma pipe binding).
// Tiling (R2's proven shape): kg=tid>>4 owns k in {kg+8i}; dg=tid&15 owns
// d pairs {2dg,2dg+1} (+32j). Weights in natural [c][d] layout (LDS.64 pair
// over adjacent d, 16 distinct 8B banks -> conflict-free).
__global__ void __launch_bounds__(128) k_mlp(
    const float* __restrict__ W1, const float* __restrict__ b1,
    const float* __restrict__ W2, const float* __restrict__ b2,
    const float* __restrict__ W3, const float* __restrict__ b3,
    float* __restrict__ out)
{
    extern __shared__ float sm[];
    float* sW1  = sm;                 // 67*64  = 4288
    float* sW2  = sW1 + 4288;         // 64*64  = 4096
    float* sW3  = sW2 + 4096;         // 64*128 = 8192
    float* sb1  = sW3 + 8192;         // 64
    float* sb2  = sb1 + 64;           // 64
    float* sb3  = sb2 + 64;           // 128
    ull*   dupA = (ull*)(sb3 + 128);  // 32 x SU ull = 4416 floats
    ull*   dupB = dupA + 32*SU;       // 4416 floats
    float* red  = (float*)(dupB + 32*SU);  // 8*128 = 1024
    const int tid = threadIdx.x;

    for (int i = tid; i < 4288; i += 128) sW1[i] = W1[i];
    for (int i = tid; i < 4096; i += 128) sW2[i] = W2[i];
    for (int i = tid; i < 8192; i += 128) sW3[i] = W3[i];
    if (tid < 64) { sb1[tid] = b1[tid]; sb2[tid] = b2[tid]; }
    sb3[tid] = b3[tid];
    __syncthreads();

    const int dg = tid & 15;          // d-pair lane (0..15)
    const int kg = tid >> 4;          // k group (0..7)
    const int kq = tid >> 2;          // gather: k (0..31)
    const int c0 = tid & 3;           // gather: lane within k

    for (int cent = blockIdx.x; cent < BB*SS; cent += gridDim.x) {
        const int b  = cent >> 12;
        const int s  = cent & (SS-1);
        const int bN = b * NN;

        // ---- gather g[k][0:67] (duplicated pairs) into dupA ----
        {
            int n = g_idx[cent*KK + kq];
            float4 p   = g_pts[bN + n];
            float4 ctr = g_pts[bN + s];
            ull* row = dupA + kq*SU;
            if      (c0 == 0) { float v = p.x - ctr.x; row[0] = pk2(v, v); }
            else if (c0 == 1) { float v = p.y - ctr.y; row[1] = pk2(v, v); }
            else if (c0 == 2) { float v = p.z - ctr.z; row[2] = pk2(v, v); }
            const float* fr = g_featT + (size_t)(bN + n) * CC;
            #pragma unroll
            for (int i2 = 0; i2 < 16; i2++) {
                int f = c0 + 4*i2;
                float v = fr[f];
                row[3 + f] = pk2(v, v);
            }
        }
        __syncthreads();

        // ---- layer 1: dupA(67) -> dupB(64), relu ----
        {
            ull acc[4][2];
            ull bi0 = ldp(sb1 + 2*dg), bi1 = ldp(sb1 + 2*dg + 32);
            #pragma unroll
            for (int i = 0; i < 4; i++) { acc[i][0] = bi0; acc[i][1] = bi1; }
            const ull* a0 = dupA + (kg     )*SU;
            const ull* a1 = dupA + (kg +  8)*SU;
            const ull* a2 = dupA + (kg + 16)*SU;
            const ull* a3 = dupA + (kg + 24)*SU;
            for (int c = 0; c < CIN; c++) {
                ull wv0 = ldp(sW1 + c*64 + 2*dg);
                ull wv1 = ldp(sW1 + c*64 + 2*dg + 32);
                ull g0 = a0[c], g1 = a1[c], g2 = a2[c], g3 = a3[c];
                acc[0][0] = ffma2(g0, wv0, acc[0][0]);
                acc[0][1] = ffma2(g0, wv1, acc[0][1]);
                acc[1][0] = ffma2(g1, wv0, acc[1][0]);
                acc[1][1] = ffma2(g1, wv1, acc[1][1]);
                acc[2][0] = ffma2(g2, wv0, acc[2][0]);
                acc[2][1] = ffma2(g2, wv1, acc[2][1]);
                acc[3][0] = ffma2(g3, wv0, acc[3][0]);
                acc[3][1] = ffma2(g3, wv1, acc[3][1]);
            }
            #pragma unroll
            for (int i = 0; i < 4; i++)
                #pragma unroll
                for (int j = 0; j < 2; j++) {
                    float lo, hi; upk2(acc[i][j], lo, hi);
                    lo = fmaxf(lo, 0.f); hi = fmaxf(hi, 0.f);
                    ull* row = dupB + (kg + 8*i)*SU;
                    row[2*dg + 32*j]     = pk2(lo, lo);
                    row[2*dg + 32*j + 1] = pk2(hi, hi);
                }
        }
        __syncthreads();

        // ---- layer 2: dupB(64) -> dupA(64), relu ----
        {
            ull acc[4][2];
            ull bi0 = ldp(sb2 + 2*dg), bi1 = ldp(sb2 + 2*dg + 32);
            #pragma unroll
            for (int i = 0; i < 4; i++) { acc[i][0] = bi0; acc[i][1] = bi1; }
            const ull* a0 = dupB + (kg     )*SU;
            const ull* a1 = dupB + (kg +  8)*SU;
            const ull* a2 = dupB + (kg + 16)*SU;
            const ull* a3 = dupB + (kg + 24)*SU;
            for (int c = 0; c < 64; c++) {
                ull wv0 = ldp(sW2 + c*64 + 2*dg);
                ull wv1 = ldp(sW2 + c*64 + 2*dg + 32);
                ull g0 = a0[c], g1 = a1[c], g2 = a2[c], g3 = a3[c];
                acc[0][0] = ffma2(g0, wv0, acc[0][0]);
                acc[0][1] = ffma2(g0, wv1, acc[0][1]);
                acc[1][0] = ffma2(g1, wv0, acc[1][0]);
                acc[1][1] = ffma2(g1, wv1, acc[1][1]);
                acc[2][0] = ffma2(g2, wv0, acc[2][0]);
                acc[2][1] = ffma2(g2, wv1, acc[2][1]);
                acc[3][0] = ffma2(g3, wv0, acc[3][0]);
                acc[3][1] = ffma2(g3, wv1, acc[3][1]);
            }
            #pragma unroll
            for (int i = 0; i < 4; i++)
                #pragma unroll
                for (int j = 0; j < 2; j++) {
                    float lo, hi; upk2(acc[i][j], lo, hi);
                    lo = fmaxf(lo, 0.f); hi = fmaxf(hi, 0.f);
                    ull* row = dupA + (kg + 8*i)*SU;
                    row[2*dg + 32*j]     = pk2(lo, lo);
                    row[2*dg + 32*j + 1] = pk2(hi, hi);
                }
        }
        __syncthreads();

        // ---- layer 3: dupA(64) -> 128 outs, relu+partial max over 4 k ----
        {
            ull acc[4][4];
            #pragma unroll
            for (int j = 0; j < 4; j++) {
                ull bi = ldp(sb3 + 2*dg + 32*j);
                #pragma unroll
                for (int i = 0; i < 4; i++) acc[i][j] = bi;
            }
            const ull* a0 = dupA + (kg     )*SU;
            const ull* a1 = dupA + (kg +  8)*SU;
            const ull* a2 = dupA + (kg + 16)*SU;
            const ull* a3 = dupA + (kg + 24)*SU;
            for (int c = 0; c < 64; c++) {
                ull wv[4];
                #pragma unroll
                for (int j = 0; j < 4; j++) wv[j] = ldp(sW3 + c*128 + 2*dg + 32*j);
                ull g0 = a0[c], g1 = a1[c], g2 = a2[c], g3 = a3[c];
                #pragma unroll
                for (int j = 0; j < 4; j++) {
                    acc[0][j] = ffma2(g0, wv[j], acc[0][j]);
                    acc[1][j] = ffma2(g1, wv[j], acc[1][j]);
                    acc[2][j] = ffma2(g2, wv[j], acc[2][j]);
                    acc[3][j] = ffma2(g3, wv[j], acc[3][j]);
                }
            }
            #pragma unroll
            for (int j = 0; j < 4; j++) {
                float l0, h0, l1, h1, l2, h2, l3, h3;
                upk2(acc[0][j], l0, h0); upk2(acc[1][j], l1, h1);
                upk2(acc[2][j], l2, h2); upk2(acc[3][j], l3, h3);
                float ml = fmaxf(fmaxf(fmaxf(l0,0.f), fmaxf(l1,0.f)),
                                 fmaxf(fmaxf(l2,0.f), fmaxf(l3,0.f)));
                float mh = fmaxf(fmaxf(fmaxf(h0,0.f), fmaxf(h1,0.f)),
                                 fmaxf(fmaxf(h2,0.f), fmaxf(h3,0.f)));
                *(float2*)&red[kg*128 + 2*dg + 32*j] = make_float2(ml, mh);
            }
        }
        __syncthreads();

        // ---- final max across the 8 k-groups; write new_features [B,128,S] ----
        {
            float m = red[tid];
            #pragma unroll
            for (int g = 1; g < 8; g++) m = fmaxf(m, red[g*128 + tid]);
            out[OUT_F + (size_t)b*H3*SS + (size_t)tid*SS + s] = m;
        }
        __syncthreads();
    }
}

// ---------------------------------------------------------------------------
extern "C" void kernel_launch(void* const* d_in, const int* in_sizes, int n_in,
                              void* d_out, int out_size) {
    (void)in_sizes; (void)n_in; (void)out_size;
    const float* xyz  = (const float*)d_in[0];
    const float* feat = (const float*)d_in[1];
    const float* W1   = (const float*)d_in[2];
    const float* b1   = (const float*)d_in[3];
    const float* W2   = (const float*)d_in[4];
    const float* b2   = (const float*)d_in[5];
    const float* W3   = (const float*)d_in[6];
    const float* b3   = (const float*)d_in[7];
    float* out = (float*)d_out;

    // smem floats: 4288+4096+8192+64+64+128 + 4416 + 4416 + 1024 = 26688 -> 106752 B
    const int smem_mlp = 26688 * 4;
    cudaFuncSetAttribute(k_mlp, cudaFuncAttributeMaxDynamicSharedMemorySize, smem_mlp);

    k_prep<<<(BB*NN + 255)/256, 256>>>(xyz);
    k_trans<<<dim3(NN/32, CC/32, BB), dim3(32, 8)>>>(feat);
    k_outs<<<(BB*SS + 255)/256, 256>>>(xyz, out);
    k_ball<<<888, 256>>>();
    k_mlp<<<296, 128, smem_mlp>>>(W1, b1, W2, b2, W3, b3, out);
}

// round 5
// speedup vs baseline: 1.0783x; 1.0783x over previous
#include <cuda_runtime.h>

// Problem constants (fixed by setup_inputs)
#define BB   2
#define NN   16384
#define CC   64
#define SS   4096
#define KK   32
#define R2   0.16f
#define CIN  67
#define H3   128

#define OUT_F (BB*SS*3)              /* 24576  : new_xyz region     */
#define OUT_I (OUT_F + BB*H3*SS)     /* 1073152: samp_idx region    */

#define CPG   8                      /* centroids per block group        */
#define ROWS  (CPG*KK)               /* 256 rows per group               */
#define GRPS  (BB*SS/CPG)            /* 1024 groups                      */
#define ASTR  258                    /* act row stride (floats), even    */
#define ASTU  129                    /* act row stride (ull)             */

// Scratch (device globals — no allocation allowed)
__device__ float4 g_pts[BB*NN];          // x,y,z,|p|^2
__device__ float  g_featT[BB*NN*CC];     // [B][N][C]
__device__ int    g_idx[BB*SS*KK];       // ball query result

// ---- packed f32x2 helpers (FFMA2 via PTX) ---------------------------------
typedef unsigned long long ull;
__device__ __forceinline__ ull pk2(float lo, float hi) {
    ull r; asm("mov.b64 %0,{%1,%2};" : "=l"(r) : "f"(lo), "f"(hi)); return r;
}
__device__ __forceinline__ void upk2(ull v, float& lo, float& hi) {
    asm("mov.b64 {%0,%1},%2;" : "=f"(lo), "=f"(hi) : "l"(v));
}
__device__ __forceinline__ ull ffma2(ull a, ull b, ull c) {
    ull d; asm("fma.rn.f32x2 %0,%1,%2,%3;" : "=l"(d) : "l"(a), "l"(b), "l"(c));
    return d;
}
__device__ __forceinline__ ull ldp(const float* p) {   // aligned smem pair
    return *reinterpret_cast<const ull*>(p);
}

// ---------------------------------------------------------------------------
__global__ void k_prep(const float* __restrict__ xyz) {
    int i = blockIdx.x * blockDim.x + threadIdx.x;
    if (i < BB*NN) {
        float x = xyz[3*i+0], y = xyz[3*i+1], z = xyz[3*i+2];
        g_pts[i] = make_float4(x, y, z, fmaf(z, z, fmaf(y, y, x*x)));
    }
}

// Transpose features [B,C,N] -> [B,N,C]
__global__ void k_trans(const float* __restrict__ feat) {
    __shared__ float tile[32][33];
    int b  = blockIdx.z;
    int n0 = blockIdx.x * 32, c0 = blockIdx.y * 32;
    int tx = threadIdx.x, ty = threadIdx.y;
    #pragma unroll
    for (int i = ty; i < 32; i += 8)
        tile[i][tx] = feat[(size_t)b*CC*NN + (size_t)(c0+i)*NN + (n0+tx)];
    __syncthreads();
    #pragma unroll
    for (int i = ty; i < 32; i += 8)
        g_featT[(size_t)b*NN*CC + (size_t)(n0+i)*CC + (c0+tx)] = tile[tx][i];
}

// new_xyz copy + samp_idx
__global__ void k_outs(const float* __restrict__ xyz, float* __restrict__ out) {
    int i = blockIdx.x * blockDim.x + threadIdx.x;
    if (i < BB*SS) {
        int b = i / SS, s = i % SS;
        out[3*i+0] = xyz[(size_t)(b*NN+s)*3 + 0];
        out[3*i+1] = xyz[(size_t)(b*NN+s)*3 + 1];
        out[3*i+2] = xyz[(size_t)(b*NN+s)*3 + 2];
        out[OUT_I + i] = (float)s;
    }
}

// ---------------------------------------------------------------------------
// Ball query (R2's proven version): one warp per centroid, x4 unroll, static
// schedule. Ordered scan; ballot+popc assigns first KK in-index-order hits;
// early exit every 128 points. Matches reference semantics exactly.
__global__ void k_ball() {
    __shared__ int sbuf[8][KK];
    int w    = threadIdx.x >> 5;
    int lane = threadIdx.x & 31;
    int gw   = blockIdx.x * 8 + w;
    int b    = gw / SS, s = gw % SS;
    int base0 = b * NN;
    float4 c4 = g_pts[base0 + s];
    unsigned lmask = (1u << lane) - 1u;
    unsigned lbit  = 1u << lane;
    int cnt = 0;
    for (int base = 0; base < NN; base += 128) {
        float4 p0 = g_pts[base0 + base + lane];
        float4 p1 = g_pts[base0 + base + 32  + lane];
        float4 p2 = g_pts[base0 + base + 64  + lane];
        float4 p3 = g_pts[base0 + base + 96  + lane];
        float d0 = c4.w + p0.w - 2.0f*(c4.x*p0.x + c4.y*p0.y + c4.z*p0.z);
        float d1 = c4.w + p1.w - 2.0f*(c4.x*p1.x + c4.y*p1.y + c4.z*p1.z);
        float d2 = c4.w + p2.w - 2.0f*(c4.x*p2.x + c4.y*p2.y + c4.z*p2.z);
        float d3 = c4.w + p3.w - 2.0f*(c4.x*p3.x + c4.y*p3.y + c4.z*p3.z);
        unsigned m0 = __ballot_sync(0xffffffffu, d0 < R2);
        unsigned m1 = __ballot_sync(0xffffffffu, d1 < R2);
        unsigned m2 = __ballot_sync(0xffffffffu, d2 < R2);
        unsigned m3 = __ballot_sync(0xffffffffu, d3 < R2);
        if (m0 & lbit) {
            int pos = cnt + __popc(m0 & lmask);
            if (pos < KK) sbuf[w][pos] = base + lane;
        }
        cnt += __popc(m0);
        if (m1 & lbit) {
            int pos = cnt + __popc(m1 & lmask);
            if (pos < KK) sbuf[w][pos] = base + 32 + lane;
        }
        cnt += __popc(m1);
        if (m2 & lbit) {
            int pos = cnt + __popc(m2 & lmask);
            if (pos < KK) sbuf[w][pos] = base + 64 + lane;
        }
        cnt += __popc(m2);
        if (m3 & lbit) {
            int pos = cnt + __popc(m3 & lmask);
            if (pos < KK) sbuf[w][pos] = base + 96 + lane;
        }
        cnt += __popc(m3);
        if (cnt >= KK) break;
    }
    __syncwarp();
    int v = 0;
    if (cnt > 0) {
        int first = sbuf[w][0];
        v = (lane < cnt) ? sbuf[w][lane] : first;
    }
    g_idx[gw*KK + lane] = v;
}

// ---------------------------------------------------------------------------
// Fused gather + 3-layer MLP + max-pool, 8 centroids per block iteration.
// Activations stored [c][row] (row = cent_local*32 + k, 256 rows, stride 258).
// FFMA2 lanes = adjacent rows (k, k+1): act LDS.64 pairs, weight scalar
// broadcast + dup-pack (hidden on alu pipe). Thread tile 8 rows x 8 d ->
// 1.0 B smem traffic per scalar FMA; LDS and FFMA2 floors both ~120us.
// tid = dgp*32 + rpg: dgp(0..7) = d group & cent for gather, rpg(0..31).
__global__ void __launch_bounds__(256, 1) k_mlp(
    const float* __restrict__ W1, const float* __restrict__ b1,
    const float* __restrict__ W2, const float* __restrict__ b2,
    const float* __restrict__ W3, const float* __restrict__ b3,
    float* __restrict__ out)
{
    extern __shared__ float sm[];
    float* sW1  = sm;                 // 67*64  = 4288
    float* sW2  = sW1 + 4288;         // 64*64  = 4096
    float* sW3  = sW2 + 4096;         // 64*128 = 8192
    float* sb1  = sW3 + 8192;         // 64
    float* sb2  = sb1 + 64;           // 64
    float* sb3  = sb2 + 64;           // 128
    float* actA = sb3 + 128;          // 67 x 258 = 17286
    float* actB = actA + 67*ASTR;     // 64 x 258 = 16512
    const int tid = threadIdx.x;
    const int dgp = tid >> 5;         // 0..7 (= warp id)
    const int rpg = tid & 31;         // 0..31

    for (int i = tid; i < 4288; i += 256) sW1[i] = W1[i];
    for (int i = tid; i < 4096; i += 256) sW2[i] = W2[i];
    for (int i = tid; i < 8192; i += 256) sW3[i] = W3[i];
    if (tid < 64)  { sb1[tid] = b1[tid]; sb2[tid] = b2[tid]; }
    if (tid < 128) sb3[tid] = b3[tid];
    __syncthreads();

    for (int grp = blockIdx.x; grp < GRPS; grp += gridDim.x) {
        // ---- gather: thread = row (cent_local = dgp, k = rpg) ----
        {
            const int cent = grp*CPG + dgp;
            const int b  = cent >> 12;
            const int s  = cent & (SS-1);
            const int bN = b * NN;
            const int row = tid;
            int n = g_idx[cent*KK + rpg];
            float4 p   = g_pts[bN + n];
            float4 ctr = g_pts[bN + s];
            actA[0*ASTR + row] = p.x - ctr.x;
            actA[1*ASTR + row] = p.y - ctr.y;
            actA[2*ASTR + row] = p.z - ctr.z;
            const float4* fq = (const float4*)(g_featT + (size_t)(bN + n) * CC);
            #pragma unroll
            for (int q = 0; q < 16; q++) {
                float4 f4 = fq[q];
                actA[(3 + 4*q    )*ASTR + row] = f4.x;
                actA[(4 + 4*q    )*ASTR + row] = f4.y;
                actA[(5 + 4*q    )*ASTR + row] = f4.z;
                actA[(6 + 4*q    )*ASTR + row] = f4.w;
            }
        }
        __syncthreads();

        // ---- layer 1: actA(67 x 256) -> actB(64 x 256), relu ----
        {
            ull acc[4][8];
            #pragma unroll
            for (int j = 0; j < 8; j++) {
                float bv = sb1[dgp + 8*j];
                ull bb = pk2(bv, bv);
                #pragma unroll
                for (int i = 0; i < 4; i++) acc[i][j] = bb;
            }
            #pragma unroll 2
            for (int c = 0; c < CIN; c++) {
                ull av[4];
                #pragma unroll
                for (int i = 0; i < 4; i++)
                    av[i] = ldp(actA + c*ASTR + 2*(rpg + 32*i));
                ull wd[8];
                #pragma unroll
                for (int j = 0; j < 8; j++) {
                    float w = sW1[c*64 + dgp + 8*j];
                    wd[j] = pk2(w, w);
                }
                #pragma unroll
                for (int i = 0; i < 4; i++)
                    #pragma unroll
                    for (int j = 0; j < 8; j++)
                        acc[i][j] = ffma2(av[i], wd[j], acc[i][j]);
            }
            ull* outB = (ull*)actB;
            #pragma unroll
            for (int i = 0; i < 4; i++)
                #pragma unroll
                for (int j = 0; j < 8; j++) {
                    float lo, hi; upk2(acc[i][j], lo, hi);
                    lo = fmaxf(lo, 0.f); hi = fmaxf(hi, 0.f);
                    outB[(size_t)(dgp + 8*j)*ASTU + rpg + 32*i] = pk2(lo, hi);
                }
        }
        __syncthreads();

        // ---- layer 2: actB(64 x 256) -> actA(64 x 256), relu ----
        {
            ull acc[4][8];
            #pragma unroll
            for (int j = 0; j < 8; j++) {
                float bv = sb2[dgp + 8*j];
                ull bb = pk2(bv, bv);
                #pragma unroll
                for (int i = 0; i < 4; i++) acc[i][j] = bb;
            }
            #pragma unroll 2
            for (int c = 0; c < 64; c++) {
                ull av[4];
                #pragma unroll
                for (int i = 0; i < 4; i++)
                    av[i] = ldp(actB + c*ASTR + 2*(rpg + 32*i));
                ull wd[8];
                #pragma unroll
                for (int j = 0; j < 8; j++) {
                    float w = sW2[c*64 + dgp + 8*j];
                    wd[j] = pk2(w, w);
                }
                #pragma unroll
                for (int i = 0; i < 4; i++)
                    #pragma unroll
                    for (int j = 0; j < 8; j++)
                        acc[i][j] = ffma2(av[i], wd[j], acc[i][j]);
            }
            ull* outA = (ull*)actA;
            #pragma unroll
            for (int i = 0; i < 4; i++)
                #pragma unroll
                for (int j = 0; j < 8; j++) {
                    float lo, hi; upk2(acc[i][j], lo, hi);
                    lo = fmaxf(lo, 0.f); hi = fmaxf(hi, 0.f);
                    outA[(size_t)(dgp + 8*j)*ASTU + rpg + 32*i] = pk2(lo, hi);
                }
        }
        __syncthreads();

        // ---- layer 3: actA(64 x 256) -> 128 d, relu + max over k, 2 halves ----
        #pragma unroll 1
        for (int h = 0; h < 2; h++) {
            ull acc[4][8];
            #pragma unroll
            for (int j = 0; j < 8; j++) {
                float bv = sb3[dgp + 8*j + 64*h];
                ull bb = pk2(bv, bv);
                #pragma unroll
                for (int i = 0; i < 4; i++) acc[i][j] = bb;
            }
            #pragma unroll 2
            for (int c = 0; c < 64; c++) {
                ull av[4];
                #pragma unroll
                for (int i = 0; i < 4; i++)
                    av[i] = ldp(actA + c*ASTR + 2*(rpg + 32*i));
                ull wd[8];
                #pragma unroll
                for (int j = 0; j < 8; j++) {
                    float w = sW3[c*128 + dgp + 8*j + 64*h];
                    wd[j] = pk2(w, w);
                }
                #pragma unroll
                for (int i = 0; i < 4; i++)
                    #pragma unroll
                    for (int j = 0; j < 8; j++)
                        acc[i][j] = ffma2(av[i], wd[j], acc[i][j]);
            }
            // relu + lane-pair max + butterfly max over rpg%16 -> per-cent max
            #pragma unroll
            for (int i = 0; i < 4; i++) {
                #pragma unroll
                for (int j = 0; j < 8; j++) {
                    float lo, hi; upk2(acc[i][j], lo, hi);
                    float m = fmaxf(fmaxf(lo, 0.f), fmaxf(hi, 0.f));
                    m = fmaxf(m, __shfl_xor_sync(0xffffffffu, m, 1));
                    m = fmaxf(m, __shfl_xor_sync(0xffffffffu, m, 2));
                    m = fmaxf(m, __shfl_xor_sync(0xffffffffu, m, 4));
                    m = fmaxf(m, __shfl_xor_sync(0xffffffffu, m, 8));
                    if ((rpg & 15) == 0) {
                        int cent_local = 2*i + (rpg >> 4);
                        int cent = grp*CPG + cent_local;
                        int b = cent >> 12, s = cent & (SS-1);
                        int d = dgp + 8*j + 64*h;
                        out[OUT_F + (size_t)b*H3*SS + (size_t)d*SS + s] = m;
                    }
                }
            }
        }
        __syncthreads();   // actA reused by next gather
    }
}

// ---------------------------------------------------------------------------
extern "C" void kernel_launch(void* const* d_in, const int* in_sizes, int n_in,
                              void* d_out, int out_size) {
    (void)in_sizes; (void)n_in; (void)out_size;
    const float* xyz  = (const float*)d_in[0];
    const float* feat = (const float*)d_in[1];
    const float* W1   = (const float*)d_in[2];
    const float* b1   = (const float*)d_in[3];
    const float* W2   = (const float*)d_in[4];
    const float* b2   = (const float*)d_in[5];
    const float* W3   = (const float*)d_in[6];
    const float* b3   = (const float*)d_in[7];
    float* out = (float*)d_out;

    // smem floats: 4288+4096+8192+64+64+128 + 17286 + 16512 = 50630 -> 202520 B
    const int smem_mlp = 50630 * 4;
    cudaFuncSetAttribute(k_mlp, cudaFuncAttributeMaxDynamicSharedMemorySize, smem_mlp);

    k_prep<<<(BB*NN + 255)/256, 256>>>(xyz);
    k_trans<<<dim3(NN/32, CC/32, BB), dim3(32, 8)>>>(feat);
    k_outs<<<(BB*SS + 255)/256, 256>>>(xyz, out);
    k_ball<<<(BB*SS)/8, 256>>>();
    k_mlp<<<148, 256, smem_mlp>>>(W1, b1, W2, b2, W3, b3, out);
}